// round 3
// baseline (speedup 1.0000x reference)
#include <cuda_runtime.h>

namespace {

constexpr int NSAMP = 2000;
constexpr int NGRAD = 10000;
constexpr int NSOAP = 6 * 32 * 32;   // 6144
constexpr int VSZ   = 36 * 32;       // sum_l (2l+1) * 32 = 1152

__constant__ float FAC[6] = {
    1.0f,
    0.57735026918962576f,   // 1/sqrt(3)
    0.44721359549995794f,   // 1/sqrt(5)
    0.37796447300922722f,   // 1/sqrt(7)
    0.33333333333333333f,   // 1/sqrt(9)
    0.30151134457776363f    // 1/sqrt(11)
};

// Load-balanced tile schedules. A "unit" = 64 threads. Work per tile ~ (2l+1).
// Grad kernel: 18 tiles (x,l). Units 0..2 take the heavy l=5,4,3 tiles of one x
// each (27 m-rows); unit 3 takes all nine l<=2 tiles (27 m-rows).
__constant__ int G_USTART[5] = {0, 3, 6, 9, 18};
__constant__ int G_TX[18] = {0,0,0, 1,1,1, 2,2,2, 0,1,2, 0,1,2, 0,1,2};
__constant__ int G_TL[18] = {5,4,3, 5,4,3, 5,4,3, 2,2,2, 1,1,1, 0,0,0};

// Values kernel: 6 tiles (l). 11 / 9 / 7+1 / 5+3 m-rows per unit.
__constant__ int V_USTART[5] = {0, 1, 2, 4, 6};
__constant__ int V_TL[6] = {5, 4, 3, 0, 2, 1};

__device__ __forceinline__ void f4_to_arr(const float* p, float a[4]) {
    float4 t = *reinterpret_cast<const float4*>(p);
    a[0] = t.x; a[1] = t.y; a[2] = t.z; a[3] = t.w;
}

} // namespace

// ---------------------------------------------------------------------------
// datafull_grad part: out[i, x, l*1024 + a*32 + b] =
//   sum_m g[i,x,m,a] * (fac_l * v[j,m,b]) + (fac_l * v[j,m,a]) * g[i,x,m,b]
// with j = grad_sample_idx[i].
// ---------------------------------------------------------------------------
__global__ __launch_bounds__(256)
void PowerSpectrum_grad_kernel(
    const float* __restrict__ v0, const float* __restrict__ v1,
    const float* __restrict__ v2, const float* __restrict__ v3,
    const float* __restrict__ v4, const float* __restrict__ v5,
    const float* __restrict__ g0, const float* __restrict__ g1,
    const float* __restrict__ g2, const float* __restrict__ g3,
    const float* __restrict__ g4, const float* __restrict__ g5,
    const int* __restrict__ idx,
    float* __restrict__ out)
{
    __shared__ __align__(16) float vs[VSZ];        // factor * v[j], all l packed
    __shared__ __align__(16) float gs[3 * VSZ];    // g[i, x], x = 0..2

    const int i   = blockIdx.x;
    const int tid = threadIdx.x;
    const int j   = __ldg(idx + i);

    const float* vptr[6] = {v0, v1, v2, v3, v4, v5};
    const float* gptr[6] = {g0, g1, g2, g3, g4, g5};

    // Stage factor-scaled values rows: vs[l*l*32 + m*32 + c]
    #pragma unroll
    for (int l = 0; l < 6; l++) {
        const int n4 = ((2 * l + 1) * 32) / 4;
        const float4* src = reinterpret_cast<const float4*>(vptr[l]) + (size_t)j * n4;
        float4* dst = reinterpret_cast<float4*>(vs + l * l * 32);
        const float f = FAC[l];
        for (int t = tid; t < n4; t += 256) {
            float4 u = src[t];
            dst[t] = make_float4(f * u.x, f * u.y, f * u.z, f * u.w);
        }
    }
    // Stage gradient rows for all 3 cartesian components (contiguous in gmem).
    #pragma unroll
    for (int l = 0; l < 6; l++) {
        const int n4 = ((2 * l + 1) * 32) / 4;
        const float4* src = reinterpret_cast<const float4*>(gptr[l]) + (size_t)i * 3 * n4;
        for (int t = tid; t < 3 * n4; t += 256) {
            const int x  = t / n4;
            const int r4 = t - x * n4;
            reinterpret_cast<float4*>(gs + x * VSZ + l * l * 32)[r4] = src[t];
        }
    }
    __syncthreads();

    const int unit = tid >> 6;
    const int ut   = tid & 63;
    const int a0   = (ut >> 3) * 4;  // 0,4,...,28
    const int b0   = (ut & 7) * 4;   // 0,4,...,28

    const int kend = G_USTART[unit + 1];
    for (int k = G_USTART[unit]; k < kend; k++) {
        const int x  = G_TX[k];
        const int l  = G_TL[k];
        const int nm = 2 * l + 1;
        const float* V = vs + l * l * 32;
        const float* G = gs + x * VSZ + l * l * 32;

        float acc[4][4];
        #pragma unroll
        for (int p = 0; p < 4; p++)
            #pragma unroll
            for (int q = 0; q < 4; q++) acc[p][q] = 0.0f;

        for (int m = 0; m < nm; m++) {
            float va[4], vb[4], ga[4], gb[4];
            f4_to_arr(V + m * 32 + a0, va);
            f4_to_arr(V + m * 32 + b0, vb);
            f4_to_arr(G + m * 32 + a0, ga);
            f4_to_arr(G + m * 32 + b0, gb);
            #pragma unroll
            for (int p = 0; p < 4; p++)
                #pragma unroll
                for (int q = 0; q < 4; q++)
                    acc[p][q] += ga[p] * vb[q] + va[p] * gb[q];
        }

        float* O = out + ((size_t)i * 3 + x) * NSOAP + l * 1024 + a0 * 32 + b0;
        #pragma unroll
        for (int p = 0; p < 4; p++)
            *reinterpret_cast<float4*>(O + p * 32) =
                make_float4(acc[p][0], acc[p][1], acc[p][2], acc[p][3]);
    }
}

// ---------------------------------------------------------------------------
// datafull part: out[i, l*1024 + a*32 + b] = fac_l * sum_m v[i,m,a] * v[i,m,b]
// ---------------------------------------------------------------------------
__global__ __launch_bounds__(256)
void PowerSpectrum_val_kernel(
    const float* __restrict__ v0, const float* __restrict__ v1,
    const float* __restrict__ v2, const float* __restrict__ v3,
    const float* __restrict__ v4, const float* __restrict__ v5,
    float* __restrict__ out)
{
    __shared__ __align__(16) float vs[VSZ];   // raw v[i], all l packed

    const int i   = blockIdx.x;
    const int tid = threadIdx.x;
    const float* vptr[6] = {v0, v1, v2, v3, v4, v5};

    #pragma unroll
    for (int l = 0; l < 6; l++) {
        const int n4 = ((2 * l + 1) * 32) / 4;
        const float4* src = reinterpret_cast<const float4*>(vptr[l]) + (size_t)i * n4;
        float4* dst = reinterpret_cast<float4*>(vs + l * l * 32);
        for (int t = tid; t < n4; t += 256) dst[t] = src[t];
    }
    __syncthreads();

    const int unit = tid >> 6;
    const int ut   = tid & 63;
    const int a0   = (ut >> 3) * 4;
    const int b0   = (ut & 7) * 4;

    const int kend = V_USTART[unit + 1];
    for (int k = V_USTART[unit]; k < kend; k++) {
        const int l  = V_TL[k];
        const int nm = 2 * l + 1;
        const float* V = vs + l * l * 32;
        const float f = FAC[l];

        float acc[4][4];
        #pragma unroll
        for (int p = 0; p < 4; p++)
            #pragma unroll
            for (int q = 0; q < 4; q++) acc[p][q] = 0.0f;

        for (int m = 0; m < nm; m++) {
            float va[4], vb[4];
            f4_to_arr(V + m * 32 + a0, va);
            f4_to_arr(V + m * 32 + b0, vb);
            #pragma unroll
            for (int p = 0; p < 4; p++)
                #pragma unroll
                for (int q = 0; q < 4; q++)
                    acc[p][q] += va[p] * vb[q];
        }

        float* O = out + (size_t)i * NSOAP + l * 1024 + a0 * 32 + b0;
        #pragma unroll
        for (int p = 0; p < 4; p++)
            *reinterpret_cast<float4*>(O + p * 32) =
                make_float4(f * acc[p][0], f * acc[p][1], f * acc[p][2], f * acc[p][3]);
    }
}

extern "C" void kernel_launch(void* const* d_in, const int* in_sizes, int n_in,
                              void* d_out, int out_size)
{
    // Classify inputs by element count — order-agnostic.
    // values_l: 2000*(2l+1)*32; grads_l: 10000*3*(2l+1)*32; idx: 10000.
    const float* v[6] = {nullptr, nullptr, nullptr, nullptr, nullptr, nullptr};
    const float* g[6] = {nullptr, nullptr, nullptr, nullptr, nullptr, nullptr};
    const int* idx = nullptr;

    for (int k = 0; k < n_in; k++) {
        const long long sz = in_sizes[k];
        bool matched = false;
        for (int l = 0; l < 6 && !matched; l++) {
            const long long vsz = (long long)NSAMP * (2 * l + 1) * 32;
            const long long gsz = (long long)NGRAD * 3 * (2 * l + 1) * 32;
            if (sz == vsz) { v[l] = (const float*)d_in[k]; matched = true; }
            else if (sz == gsz) { g[l] = (const float*)d_in[k]; matched = true; }
        }
        if (!matched && sz == NGRAD) idx = (const int*)d_in[k];
    }

    float* out = (float*)d_out;

    PowerSpectrum_val_kernel<<<NSAMP, 256>>>(
        v[0], v[1], v[2], v[3], v[4], v[5], out);

    PowerSpectrum_grad_kernel<<<NGRAD, 256>>>(
        v[0], v[1], v[2], v[3], v[4], v[5],
        g[0], g[1], g[2], g[3], g[4], g[5],
        idx, out + (size_t)NSAMP * NSOAP);
}

// round 9
// speedup vs baseline: 1.0624x; 1.0624x over previous
#include <cuda_runtime.h>

namespace {

constexpr int NSAMP = 2000;
constexpr int NGRAD = 10000;
constexpr int NSOAP = 6 * 32 * 32;   // 6144
constexpr int VSZ   = 36 * 32;       // sum_l (2l+1) * 32 = 1152

__constant__ float FAC[6] = {
    1.0f,
    0.57735026918962576f,   // 1/sqrt(3)
    0.44721359549995794f,   // 1/sqrt(5)
    0.37796447300922722f,   // 1/sqrt(7)
    0.33333333333333333f,   // 1/sqrt(9)
    0.30151134457776363f    // 1/sqrt(11)
};

// Values kernel: 6 tiles (l). 11 / 9 / 7+1 / 5+3 m-rows per unit.
__constant__ int V_USTART[5] = {0, 1, 2, 4, 6};
__constant__ int V_TL[6] = {5, 4, 3, 0, 2, 1};

__device__ __forceinline__ void f4_to_arr(const float* p, float a[4]) {
    float4 t = *reinterpret_cast<const float4*>(p);
    a[0] = t.x; a[1] = t.y; a[2] = t.z; a[3] = t.w;
}

// Closed-form triangle decode: for q in [0, 36), find ta with
// ta*(ta+1)/2 <= q, tb = q - ta*(ta+1)/2. Exact in fp32 for this range.
__device__ __forceinline__ void tri_decode(int q, int& ta, int& tb) {
    float qf = (float)(8 * q + 1);
    int t = (int)((__fsqrt_rn(qf) - 1.0f) * 0.5f);
    // Guard against fp rounding at triangle boundaries.
    if ((t + 1) * (t + 2) / 2 <= q) t++;
    if (t * (t + 1) / 2 > q) t--;
    ta = t;
    tb = q - t * (t + 1) / 2;
}

} // namespace

// ---------------------------------------------------------------------------
// datafull_grad part: out[i, x, l*1024 + a*32 + b] =
//   sum_m g[i,x,m,a] * (fac_l * v[j,m,b]) + (fac_l * v[j,m,a]) * g[i,x,m,b]
// with j = grad_sample_idx[i]. The 32x32 (a,b) block is SYMMETRIC, so we only
// compute the lower-triangle 4x4 subtiles (ta >= tb) and mirror-write the
// transposed result for off-diagonal subtiles. 648 triangle subtiles
// (x, l, ta, tb), sorted by l descending, are distributed over 256 threads
// with an arithmetic serpentine schedule:
//   e1 = tid, e2 = 511 - tid, e3 = 512 + (255 - tid)  [tid >= 120 only]
// giving per-thread weighted work (sum of nm) in [14, 17] vs ideal 15.19.
// ---------------------------------------------------------------------------
__global__ __launch_bounds__(256)
void PowerSpectrum_grad_kernel(
    const float* __restrict__ v0, const float* __restrict__ v1,
    const float* __restrict__ v2, const float* __restrict__ v3,
    const float* __restrict__ v4, const float* __restrict__ v5,
    const float* __restrict__ g0, const float* __restrict__ g1,
    const float* __restrict__ g2, const float* __restrict__ g3,
    const float* __restrict__ g4, const float* __restrict__ g5,
    const int* __restrict__ idx,
    float* __restrict__ out)
{
    __shared__ __align__(16) float vs[VSZ];        // factor * v[j], all l packed
    __shared__ __align__(16) float gs[3 * VSZ];    // g[i, x], x = 0..2

    const int i   = blockIdx.x;
    const int tid = threadIdx.x;
    const int j   = __ldg(idx + i);

    const float* vptr[6] = {v0, v1, v2, v3, v4, v5};
    const float* gptr[6] = {g0, g1, g2, g3, g4, g5};

    // Stage factor-scaled values rows: vs[l*l*32 + m*32 + c]
    #pragma unroll
    for (int l = 0; l < 6; l++) {
        const int n4 = ((2 * l + 1) * 32) / 4;
        const float4* src = reinterpret_cast<const float4*>(vptr[l]) + (size_t)j * n4;
        float4* dst = reinterpret_cast<float4*>(vs + l * l * 32);
        const float f = FAC[l];
        for (int t = tid; t < n4; t += 256) {
            float4 u = src[t];
            dst[t] = make_float4(f * u.x, f * u.y, f * u.z, f * u.w);
        }
    }
    // Stage gradient rows for all 3 cartesian components (contiguous in gmem).
    #pragma unroll
    for (int l = 0; l < 6; l++) {
        const int n4 = ((2 * l + 1) * 32) / 4;
        const float4* src = reinterpret_cast<const float4*>(gptr[l]) + (size_t)i * 3 * n4;
        for (int t = tid; t < 3 * n4; t += 256) {
            const int x  = t / n4;
            const int r4 = t - x * n4;
            reinterpret_cast<float4*>(gs + x * VSZ + l * l * 32)[r4] = src[t];
        }
    }
    __syncthreads();

    // Serpentine schedule over the 648 sorted triangle subtiles.
    int elist[3];
    int ne = 0;
    elist[ne++] = tid;
    elist[ne++] = 511 - tid;
    if (tid >= 120) elist[ne++] = 512 + (255 - tid);

    float* const outb = out + (size_t)i * 3 * NSOAP;

    for (int k = 0; k < ne; k++) {
        const int e = elist[k];
        // Decode: entries sorted l = 5..0, each l-bucket = 3x * 36 triangle.
        const int bucket = e / 108;          // 0..5
        const int l = 5 - bucket;
        int r = e - bucket * 108;
        const int x = r / 36;
        int ta, tb;
        tri_decode(r - x * 36, ta, tb);

        const int nm = 2 * l + 1;
        const float* V = vs + l * l * 32;
        const float* G = gs + x * VSZ + l * l * 32;
        const int a0 = ta * 4;
        const int b0 = tb * 4;

        float acc[4][4];
        #pragma unroll
        for (int p = 0; p < 4; p++)
            #pragma unroll
            for (int c = 0; c < 4; c++) acc[p][c] = 0.0f;

        for (int m = 0; m < nm; m++) {
            float va[4], vb[4], ga[4], gb[4];
            f4_to_arr(V + m * 32 + a0, va);
            f4_to_arr(V + m * 32 + b0, vb);
            f4_to_arr(G + m * 32 + a0, ga);
            f4_to_arr(G + m * 32 + b0, gb);
            #pragma unroll
            for (int p = 0; p < 4; p++)
                #pragma unroll
                for (int c = 0; c < 4; c++)
                    acc[p][c] += ga[p] * vb[c] + va[p] * gb[c];
        }

        float* O = outb + (size_t)x * NSOAP + l * 1024;
        // Direct subtile store: rows a0+p, cols b0..b0+3
        #pragma unroll
        for (int p = 0; p < 4; p++)
            *reinterpret_cast<float4*>(O + (a0 + p) * 32 + b0) =
                make_float4(acc[p][0], acc[p][1], acc[p][2], acc[p][3]);
        // Mirror (transposed) store for off-diagonal subtiles: rows b0+c, cols a0..a0+3
        if (ta != tb) {
            #pragma unroll
            for (int c = 0; c < 4; c++)
                *reinterpret_cast<float4*>(O + (b0 + c) * 32 + a0) =
                    make_float4(acc[0][c], acc[1][c], acc[2][c], acc[3][c]);
        }
    }
}

// ---------------------------------------------------------------------------
// datafull part: out[i, l*1024 + a*32 + b] = fac_l * sum_m v[i,m,a] * v[i,m,b]
// (only ~6% of total runtime — kept in the original full-tile form)
// ---------------------------------------------------------------------------
__global__ __launch_bounds__(256)
void PowerSpectrum_val_kernel(
    const float* __restrict__ v0, const float* __restrict__ v1,
    const float* __restrict__ v2, const float* __restrict__ v3,
    const float* __restrict__ v4, const float* __restrict__ v5,
    float* __restrict__ out)
{
    __shared__ __align__(16) float vs[VSZ];   // raw v[i], all l packed

    const int i   = blockIdx.x;
    const int tid = threadIdx.x;
    const float* vptr[6] = {v0, v1, v2, v3, v4, v5};

    #pragma unroll
    for (int l = 0; l < 6; l++) {
        const int n4 = ((2 * l + 1) * 32) / 4;
        const float4* src = reinterpret_cast<const float4*>(vptr[l]) + (size_t)i * n4;
        float4* dst = reinterpret_cast<float4*>(vs + l * l * 32);
        for (int t = tid; t < n4; t += 256) dst[t] = src[t];
    }
    __syncthreads();

    const int unit = tid >> 6;
    const int ut   = tid & 63;
    const int a0   = (ut >> 3) * 4;
    const int b0   = (ut & 7) * 4;

    const int kend = V_USTART[unit + 1];
    for (int k = V_USTART[unit]; k < kend; k++) {
        const int l  = V_TL[k];
        const int nm = 2 * l + 1;
        const float* V = vs + l * l * 32;
        const float f = FAC[l];

        float acc[4][4];
        #pragma unroll
        for (int p = 0; p < 4; p++)
            #pragma unroll
            for (int c = 0; c < 4; c++) acc[p][c] = 0.0f;

        for (int m = 0; m < nm; m++) {
            float va[4], vb[4];
            f4_to_arr(V + m * 32 + a0, va);
            f4_to_arr(V + m * 32 + b0, vb);
            #pragma unroll
            for (int p = 0; p < 4; p++)
                #pragma unroll
                for (int c = 0; c < 4; c++)
                    acc[p][c] += va[p] * vb[c];
        }

        float* O = out + (size_t)i * NSOAP + l * 1024 + a0 * 32 + b0;
        #pragma unroll
        for (int p = 0; p < 4; p++)
            *reinterpret_cast<float4*>(O + p * 32) =
                make_float4(f * acc[p][0], f * acc[p][1], f * acc[p][2], f * acc[p][3]);
    }
}

extern "C" void kernel_launch(void* const* d_in, const int* in_sizes, int n_in,
                              void* d_out, int out_size)
{
    // Classify inputs by element count — order-agnostic.
    // values_l: 2000*(2l+1)*32; grads_l: 10000*3*(2l+1)*32; idx: 10000.
    const float* v[6] = {nullptr, nullptr, nullptr, nullptr, nullptr, nullptr};
    const float* g[6] = {nullptr, nullptr, nullptr, nullptr, nullptr, nullptr};
    const int* idx = nullptr;

    for (int k = 0; k < n_in; k++) {
        const long long sz = in_sizes[k];
        bool matched = false;
        for (int l = 0; l < 6 && !matched; l++) {
            const long long vsz = (long long)NSAMP * (2 * l + 1) * 32;
            const long long gsz = (long long)NGRAD * 3 * (2 * l + 1) * 32;
            if (sz == vsz) { v[l] = (const float*)d_in[k]; matched = true; }
            else if (sz == gsz) { g[l] = (const float*)d_in[k]; matched = true; }
        }
        if (!matched && sz == NGRAD) idx = (const int*)d_in[k];
    }

    float* out = (float*)d_out;

    PowerSpectrum_val_kernel<<<NSAMP, 256>>>(
        v[0], v[1], v[2], v[3], v[4], v[5], out);

    PowerSpectrum_grad_kernel<<<NGRAD, 256>>>(
        v[0], v[1], v[2], v[3], v[4], v[5],
        g[0], g[1], g[2], g[3], g[4], g[5],
        idx, out + (size_t)NSAMP * NSOAP);
}